// round 15
// baseline (speedup 1.0000x reference)
#include <cuda_runtime.h>

#define BATCH 64
#define TT    200
#define NUM_C 2000
#define DIM   128
#define MM    50
#define MP    56          // M padded; rows 50..55 have w=0 (inert)
#define NX    4000        // distinct x = skill + 2000*answer
#define NCH   10          // time chunks
#define CL    20          // chunk length (divisible by 4)
#define SLICE 458752      // 64*56*128 scalars per chunk-slab

// ---------------- scratch (device globals; no allocation allowed) ----------
__device__ __align__(16) float g_w[NUM_C * MP];       // softmax(k·Mk^T) per skill id
__device__ __align__(16) float g_ea[NX * 256];        // [x][0:128]=e, [128:256]=a
__device__ __align__(16) float g_kf[NUM_C * DIM];     // k-part of f GEMM + f_b folded
__device__ __align__(16) float g_reads[BATCH * TT * DIM];
__device__ __align__(16) float g_fWat[DIM * DIM];     // [k][i] = f_W[i*256 + k]
__device__ __align__(16) float g_A[(NCH - 1) * SLICE]; // chunk affine: scale
__device__ __align__(16) float g_B[(NCH - 1) * SLICE]; // chunk affine: offset
__device__ __align__(16) float g_S[NCH * SLICE];       // chunk-start states

__device__ __forceinline__ float sigmoidf_(float x) { return 1.f / (1.f + __expf(-x)); }

// =====================================================================
// w table: softmax(k_emb[c] · Mk^T) over 50 slots; 125 CTAs
// =====================================================================
__global__ void k_wtable(const float* __restrict__ k_emb, const float* __restrict__ Mk) {
    __shared__ float mksh[DIM * 65];   // padded transpose, conflict-free
    __shared__ float ksh[4 * DIM];
    __shared__ float gmax[8], gsum[8];
    int tid = threadIdx.x;
    int c0 = blockIdx.x * 16;
    int m = tid & 63, cg = tid >> 6, wh = (tid >> 5) & 1;
    for (int i = tid; i < MM * DIM; i += 256) {
        int mm = i >> 7, j = i & 127;
        mksh[j * 65 + mm] = Mk[i];
    }
    for (int cl = 0; cl < 16; cl += 4) {
        int c = c0 + cl + cg;
        __syncthreads();
        for (int j = tid; j < 4 * DIM; j += 256)
            ksh[j] = k_emb[(c0 + cl + (j >> 7)) * DIM + (j & 127)];
        __syncthreads();
        float acc = 0.f;
        if (m < MM) {
            #pragma unroll 8
            for (int j = 0; j < DIM; j++) acc = fmaf(ksh[cg * DIM + j], mksh[j * 65 + m], acc);
        }
        float lg = (m < MM) ? acc : -1e30f;
        float mx = lg;
        #pragma unroll
        for (int off = 16; off; off >>= 1) mx = fmaxf(mx, __shfl_xor_sync(~0u, mx, off));
        if ((tid & 31) == 0) gmax[cg * 2 + wh] = mx;
        __syncthreads();
        mx = fmaxf(gmax[cg * 2], gmax[cg * 2 + 1]);
        float ex = (m < MM) ? __expf(lg - mx) : 0.f;
        float sv = ex;
        #pragma unroll
        for (int off = 16; off; off >>= 1) sv += __shfl_xor_sync(~0u, sv, off);
        if ((tid & 31) == 0) gsum[cg * 2 + wh] = sv;
        __syncthreads();
        float s = gsum[cg * 2] + gsum[cg * 2 + 1];
        if (m < MP) g_w[c * MP + m] = ex / s;
    }
}

// =====================================================================
// e/a table: 4000 x 256 GEMM (K=128) + activations; 125 CTAs
// =====================================================================
__global__ void k_ea(const float* __restrict__ v_emb, const float* __restrict__ e_b,
                     const float* __restrict__ a_b,
                     const float* __restrict__ e_W, const float* __restrict__ a_W) {
    __shared__ float Xs[32 * DIM];
    __shared__ __align__(16) float Ws[16 * 260];
    int row0 = blockIdx.x * 32;
    int tid = threadIdx.x;
    int tx = tid & 31, ty = tid >> 5;
    for (int i = tid; i < 32 * DIM; i += 256) Xs[i] = v_emb[row0 * DIM + i];
    float acc[4][8];
    #pragma unroll
    for (int u = 0; u < 4; u++)
        #pragma unroll
        for (int v = 0; v < 8; v++) acc[u][v] = 0.f;
    for (int kc = 0; kc < DIM; kc += 16) {
        __syncthreads();
        for (int i = tid; i < 16 * 256; i += 256) {
            int kk = i & 15, c = i >> 4;
            float v = (c < DIM) ? e_W[c * DIM + kc + kk] : a_W[(c - DIM) * DIM + kc + kk];
            Ws[kk * 260 + c] = v;
        }
        __syncthreads();
        #pragma unroll
        for (int kk = 0; kk < 16; kk++) {
            float xv[4];
            #pragma unroll
            for (int u = 0; u < 4; u++) xv[u] = Xs[(ty * 4 + u) * DIM + kc + kk];
            float4 w0 = *(const float4*)&Ws[kk * 260 + tx * 8];
            float4 w1 = *(const float4*)&Ws[kk * 260 + tx * 8 + 4];
            #pragma unroll
            for (int u = 0; u < 4; u++) {
                acc[u][0] = fmaf(xv[u], w0.x, acc[u][0]);
                acc[u][1] = fmaf(xv[u], w0.y, acc[u][1]);
                acc[u][2] = fmaf(xv[u], w0.z, acc[u][2]);
                acc[u][3] = fmaf(xv[u], w0.w, acc[u][3]);
                acc[u][4] = fmaf(xv[u], w1.x, acc[u][4]);
                acc[u][5] = fmaf(xv[u], w1.y, acc[u][5]);
                acc[u][6] = fmaf(xv[u], w1.z, acc[u][6]);
                acc[u][7] = fmaf(xv[u], w1.w, acc[u][7]);
            }
        }
    }
    int col = tx * 8;
    float barr[8];
    #pragma unroll
    for (int v = 0; v < 8; v++) {
        int cc = col + v;
        barr[v] = (cc < DIM) ? e_b[cc] : a_b[cc - DIM];
    }
    #pragma unroll
    for (int u = 0; u < 4; u++) {
        float o[8];
        #pragma unroll
        for (int v = 0; v < 8; v++) {
            float z = acc[u][v] + barr[v];
            o[v] = (col + v < DIM) ? sigmoidf_(z) : tanhf(z);
        }
        int r = row0 + ty * 4 + u;
        *(float4*)&g_ea[r * 256 + col]     = make_float4(o[0], o[1], o[2], o[3]);
        *(float4*)&g_ea[r * 256 + col + 4] = make_float4(o[4], o[5], o[6], o[7]);
    }
}

// =====================================================================
// kf table (63 CTAs) + f_W(reads-half) transpose (8 CTAs)
// =====================================================================
__global__ void k_kfT(const float* __restrict__ k_emb, const float* __restrict__ f_b,
                      const float* __restrict__ f_W) {
    __shared__ float Xs[32 * DIM];
    __shared__ __align__(16) float Ws[16 * 132];
    int bid = blockIdx.x;
    int tid = threadIdx.x;
    if (bid >= 63) {
        int base = (bid - 63) * 2048;
        #pragma unroll
        for (int j = 0; j < 8; j++) {
            int idx = base + j * 256 + tid;
            int k = idx >> 7, ii = idx & 127;
            g_fWat[idx] = f_W[ii * 256 + k];
        }
        return;
    }
    int row0 = bid * 32;
    for (int i = tid; i < 32 * DIM; i += 256) {
        int rr = i >> 7;
        Xs[i] = (row0 + rr < NUM_C) ? k_emb[row0 * DIM + i] : 0.f;
    }
    int tx = tid & 31, ty = tid >> 5;
    float acc[4][4];
    #pragma unroll
    for (int u = 0; u < 4; u++)
        #pragma unroll
        for (int v = 0; v < 4; v++) acc[u][v] = 0.f;
    for (int kc = 0; kc < DIM; kc += 16) {
        __syncthreads();
        for (int i = tid; i < 16 * DIM; i += 256) {
            int kk = i & 15, col = i >> 4;
            Ws[kk * 132 + col] = f_W[col * 256 + 128 + kc + kk];
        }
        __syncthreads();
        #pragma unroll
        for (int kk = 0; kk < 16; kk++) {
            float4 w0 = *(const float4*)&Ws[kk * 132 + tx * 4];
            #pragma unroll
            for (int u = 0; u < 4; u++) {
                float x = Xs[(ty * 4 + u) * DIM + kc + kk];
                acc[u][0] = fmaf(x, w0.x, acc[u][0]);
                acc[u][1] = fmaf(x, w0.y, acc[u][1]);
                acc[u][2] = fmaf(x, w0.z, acc[u][2]);
                acc[u][3] = fmaf(x, w0.w, acc[u][3]);
            }
        }
    }
    int col = tx * 4;
    float b0 = f_b[col], b1 = f_b[col + 1], b2 = f_b[col + 2], b3 = f_b[col + 3];
    #pragma unroll
    for (int u = 0; u < 4; u++) {
        int r = row0 + ty * 4 + u;
        if (r < NUM_C)
            *(float4*)&g_kf[r * DIM + col] =
                make_float4(acc[u][0] + b0, acc[u][1] + b1, acc[u][2] + b2, acc[u][3] + b3);
    }
}

// =====================================================================
// scanA: per-chunk affine composition. grid (9, 512) = chunk x (b*8+dsl),
// 128 threads; thread owns 7 m x 1 d. Per step per m:
//   alpha = 1 - w*e; A *= alpha; B = alpha*B + w*a.  No reduce, no output.
// R9 gather pipeline (roles, 4-slot ring, 1 sync/step).
// =====================================================================
__global__ __launch_bounds__(128) void k_scanA(const int* __restrict__ skill,
                                               const int* __restrict__ answer) {
    __shared__ int s_sk[CL], s_x[CL];
    __shared__ __align__(16) float w_sh[4][MP];
    __shared__ __align__(16) float e_sh[4][16];
    __shared__ __align__(16) float a_sh[4][16];
    int c = blockIdx.x;                  // chunk 0..8
    int bd = blockIdx.y;
    int b = bd >> 3, dsl = bd & 7;
    int dbase = dsl * 16;
    int tid = threadIdx.x;
    int wid = tid >> 5, lane = tid & 31;
    int mg = lane >> 2, dq = lane & 3;
    int ddl = wid * 4 + dq;              // 0..15 within slice
    int tbase = c * CL;

    if (tid < CL) {
        int s = skill[b * TT + tbase + tid];
        int aa = answer[b * TT + tbase + tid];
        if (aa > 1) aa = 1;
        s_sk[tid] = s;
        s_x[tid] = s + NUM_C * aa;
    }
    float A[7], B[7];
    #pragma unroll
    for (int i = 0; i < 7; i++) { A[i] = 1.f; B[i] = 0.f; }
    __syncthreads();

    bool isW = tid < MP;
    bool isE = (tid >= 64) && (tid < 80);
    bool isA = (tid >= 80) && (tid < 96);
    bool lp = isW || isE || isA;
    int eoff = isE ? (dbase + (tid - 64)) : (128 + dbase + (tid - 80));

    float pfR[4] = {0.f, 0.f, 0.f, 0.f};
    if (lp) {
        float v0;
        if (isW) {
            v0     = g_w[s_sk[0] * MP + tid];
            pfR[1] = g_w[s_sk[1] * MP + tid];
            pfR[2] = g_w[s_sk[2] * MP + tid];
            pfR[3] = g_w[s_sk[3] * MP + tid];
            w_sh[0][tid] = v0;
        } else {
            v0     = g_ea[s_x[0] * 256 + eoff];
            pfR[1] = g_ea[s_x[1] * 256 + eoff];
            pfR[2] = g_ea[s_x[2] * 256 + eoff];
            pfR[3] = g_ea[s_x[3] * 256 + eoff];
            if (isE) e_sh[0][tid - 64] = v0;
            else     a_sh[0][tid - 80] = v0;
        }
    }
    __syncthreads();

    for (int t0 = 0; t0 < CL; t0 += 4) {
        #pragma unroll
        for (int q = 0; q < 4; q++) {
            int t = t0 + q;
            float e = e_sh[q][ddl];
            float a = a_sh[q][ddl];
            #pragma unroll
            for (int i = 0; i < 7; i++) {
                float wm = w_sh[q][mg * 7 + i];
                float al = fmaf(-wm, e, 1.f);
                float be = wm * a;
                A[i] = al * A[i];
                B[i] = fmaf(al, B[i], be);
            }
            if (lp && t + 1 < CL) {
                float pv = pfR[(q + 1) & 3];
                int nb = (q + 1) & 3;
                if (isW)      w_sh[nb][tid] = pv;
                else if (isE) e_sh[nb][tid - 64] = pv;
                else          a_sh[nb][tid - 80] = pv;
            }
            if (lp && t + 4 < CL) {
                float nv;
                if (isW) nv = g_w[s_sk[t + 4] * MP + tid];
                else     nv = g_ea[s_x[t + 4] * 256 + eoff];
                pfR[q] = nv;
            }
            __syncthreads();
        }
    }
    // write composed affine for this chunk
    int base = c * SLICE + b * 7168;      // 7168 = 56*128
    #pragma unroll
    for (int i = 0; i < 7; i++) {
        int idx = base + (mg * 7 + i) * 128 + dbase + ddl;
        g_A[idx] = A[i];
        g_B[idx] = B[i];
    }
}

// =====================================================================
// scanB: sequential combine over 9 chunk maps -> chunk-start states g_S.
// 1792 CTAs x 256; one (b,m,d) scalar per thread; fully coalesced.
// =====================================================================
__global__ void k_scanB(const float* __restrict__ Mv0) {
    int gid = blockIdx.x * 256 + threadIdx.x;      // < SLICE
    int b = gid / 7168;
    int rem = gid - b * 7168;                      // m*128 + d
    int m = rem >> 7;
    float s = (m < MM) ? Mv0[rem] : 0.f;
    g_S[gid] = s;
    #pragma unroll
    for (int c = 0; c < NCH - 1; c++) {
        float Ax = g_A[c * SLICE + gid];
        float Bx = g_B[c * SLICE + gid];
        s = fmaf(Ax, s, Bx);
        g_S[(c + 1) * SLICE + gid] = s;
    }
}

// =====================================================================
// scanC: R9's proven step loop, 20 steps from chunk-start state.
// grid (10, 512); 128 threads; emits g_reads.
// =====================================================================
__global__ __launch_bounds__(128) void k_scanC(const int* __restrict__ skill,
                                               const int* __restrict__ answer) {
    __shared__ int s_sk[CL], s_x[CL];
    __shared__ __align__(16) float w_sh[4][MP];
    __shared__ __align__(16) float e_sh[4][16];
    __shared__ __align__(16) float a_sh[4][16];
    int c = blockIdx.x;                  // chunk 0..9
    int bd = blockIdx.y;
    int b = bd >> 3, dsl = bd & 7;
    int dbase = dsl * 16;
    int tid = threadIdx.x;
    int wid = tid >> 5, lane = tid & 31;
    int mg = lane >> 2, dq = lane & 3;
    int ddl = wid * 4 + dq;
    int tbase = c * CL;

    if (tid < CL) {
        int s = skill[b * TT + tbase + tid];
        int aa = answer[b * TT + tbase + tid];
        if (aa > 1) aa = 1;
        s_sk[tid] = s;
        s_x[tid] = s + NUM_C * aa;
    }
    float mv[7];
    {
        int base = c * SLICE + b * 7168;
        #pragma unroll
        for (int i = 0; i < 7; i++)
            mv[i] = g_S[base + (mg * 7 + i) * 128 + dbase + ddl];
    }
    __syncthreads();

    bool isW = tid < MP;
    bool isE = (tid >= 64) && (tid < 80);
    bool isA = (tid >= 80) && (tid < 96);
    bool lp = isW || isE || isA;
    int eoff = isE ? (dbase + (tid - 64)) : (128 + dbase + (tid - 80));

    float pfR[4] = {0.f, 0.f, 0.f, 0.f};
    if (lp) {
        float v0;
        if (isW) {
            v0     = g_w[s_sk[0] * MP + tid];
            pfR[1] = g_w[s_sk[1] * MP + tid];
            pfR[2] = g_w[s_sk[2] * MP + tid];
            pfR[3] = g_w[s_sk[3] * MP + tid];
            w_sh[0][tid] = v0;
        } else {
            v0     = g_ea[s_x[0] * 256 + eoff];
            pfR[1] = g_ea[s_x[1] * 256 + eoff];
            pfR[2] = g_ea[s_x[2] * 256 + eoff];
            pfR[3] = g_ea[s_x[3] * 256 + eoff];
            if (isE) e_sh[0][tid - 64] = v0;
            else     a_sh[0][tid - 80] = v0;
        }
    }
    __syncthreads();

    int outbase = (b * TT + tbase) * DIM + dbase + ddl;

    for (int t0 = 0; t0 < CL; t0 += 4) {
        #pragma unroll
        for (int q = 0; q < 4; q++) {
            int t = t0 + q;
            float e = e_sh[q][ddl];
            float a = a_sh[q][ddl];
            float acc = 0.f;
            #pragma unroll
            for (int i = 0; i < 7; i++) {
                float wm = w_sh[q][mg * 7 + i];
                acc = fmaf(wm, mv[i], acc);                      // PRE-update read
                mv[i] = fmaf(wm, fmaf(-e, mv[i], a), mv[i]);
            }
            acc += __shfl_xor_sync(~0u, acc, 4);
            acc += __shfl_xor_sync(~0u, acc, 8);
            acc += __shfl_xor_sync(~0u, acc, 16);
            if (mg == 0) g_reads[outbase + t * DIM] = acc;
            if (lp && t + 1 < CL) {
                float pv = pfR[(q + 1) & 3];
                int nb = (q + 1) & 3;
                if (isW)      w_sh[nb][tid] = pv;
                else if (isE) e_sh[nb][tid - 64] = pv;
                else          a_sh[nb][tid - 80] = pv;
            }
            if (lp && t + 4 < CL) {
                float nv;
                if (isW) nv = g_w[s_sk[t + 4] * MP + tid];
                else     nv = g_ea[s_x[t + 4] * 256 + eoff];
                pfR[q] = nv;
            }
            __syncthreads();
        }
    }
}

// =====================================================================
// fpred v2 (R14-proven): full fWat in 64KB dynamic smem, zero mainloop
// barriers. 199 CTAs x 64 rows, 256 threads.
// =====================================================================
#define FP_XPITCH 132
#define FP_SMEM ((64 * FP_XPITCH + DIM * DIM) * 4)
__global__ __launch_bounds__(256) void k_fpred(const int* __restrict__ skill,
                                               const float* __restrict__ p_W,
                                               const float* __restrict__ p_b,
                                               float* __restrict__ out) {
    extern __shared__ __align__(16) float dsm[];
    float* Xs = dsm;
    float* Ws = dsm + 64 * FP_XPITCH;
    __shared__ int s_kf[64], s_nx[64];
    int row0 = blockIdx.x * 64;
    int tid = threadIdx.x;

    if (tid < 64) {
        int r = row0 + tid;
        int bb = r / 199;
        int t = r - bb * 199;
        s_kf[tid] = skill[bb * TT + t];
        s_nx[tid] = skill[bb * TT + t + 1];
    }
    for (int i = tid * 4; i < DIM * DIM; i += 1024)
        *(float4*)&Ws[i] = *(const float4*)&g_fWat[i];
    {
        int row = tid >> 2, qr = tid & 3;
        int r = row0 + row;
        int bb = r / 199;
        int t = r - bb * 199;
        const float* src = &g_reads[(bb * TT + t) * DIM];
        #pragma unroll
        for (int j = 0; j < 8; j++) {
            int c4 = (qr + j * 4) * 4;
            *(float4*)&Xs[row * FP_XPITCH + c4] = *(const float4*)&src[c4];
        }
    }
    __syncthreads();

    int tx = tid & 15, ty = tid >> 4;
    float acc[4][8];
    #pragma unroll
    for (int u = 0; u < 4; u++)
        #pragma unroll
        for (int v = 0; v < 8; v++) acc[u][v] = 0.f;

    #pragma unroll 4
    for (int k = 0; k < DIM; k += 4) {
        float4 x0 = *(const float4*)&Xs[(ty * 4 + 0) * FP_XPITCH + k];
        float4 x1 = *(const float4*)&Xs[(ty * 4 + 1) * FP_XPITCH + k];
        float4 x2 = *(const float4*)&Xs[(ty * 4 + 2) * FP_XPITCH + k];
        float4 x3 = *(const float4*)&Xs[(ty * 4 + 3) * FP_XPITCH + k];
        #pragma unroll
        for (int kk = 0; kk < 4; kk++) {
            float4 w0 = *(const float4*)&Ws[(k + kk) * DIM + tx * 8];
            float4 w1 = *(const float4*)&Ws[(k + kk) * DIM + tx * 8 + 4];
            float xv[4];
            xv[0] = (kk == 0) ? x0.x : (kk == 1) ? x0.y : (kk == 2) ? x0.z : x0.w;
            xv[1] = (kk == 0) ? x1.x : (kk == 1) ? x1.y : (kk == 2) ? x1.z : x1.w;
            xv[2] = (kk == 0) ? x2.x : (kk == 1) ? x2.y : (kk == 2) ? x2.z : x2.w;
            xv[3] = (kk == 0) ? x3.x : (kk == 1) ? x3.y : (kk == 2) ? x3.z : x3.w;
            #pragma unroll
            for (int u = 0; u < 4; u++) {
                acc[u][0] = fmaf(xv[u], w0.x, acc[u][0]);
                acc[u][1] = fmaf(xv[u], w0.y, acc[u][1]);
                acc[u][2] = fmaf(xv[u], w0.z, acc[u][2]);
                acc[u][3] = fmaf(xv[u], w0.w, acc[u][3]);
                acc[u][4] = fmaf(xv[u], w1.x, acc[u][4]);
                acc[u][5] = fmaf(xv[u], w1.y, acc[u][5]);
                acc[u][6] = fmaf(xv[u], w1.z, acc[u][6]);
                acc[u][7] = fmaf(xv[u], w1.w, acc[u][7]);
            }
        }
    }
    __syncthreads();

    int col = tx * 8;
    #pragma unroll
    for (int u = 0; u < 4; u++) {
        int row = ty * 4 + u;
        int sc = s_kf[row];
        float4 k0 = *(const float4*)&g_kf[sc * DIM + col];
        float4 k1 = *(const float4*)&g_kf[sc * DIM + col + 4];
        Xs[row * FP_XPITCH + col + 0] = tanhf(acc[u][0] + k0.x);
        Xs[row * FP_XPITCH + col + 1] = tanhf(acc[u][1] + k0.y);
        Xs[row * FP_XPITCH + col + 2] = tanhf(acc[u][2] + k0.z);
        Xs[row * FP_XPITCH + col + 3] = tanhf(acc[u][3] + k0.w);
        Xs[row * FP_XPITCH + col + 4] = tanhf(acc[u][4] + k1.x);
        Xs[row * FP_XPITCH + col + 5] = tanhf(acc[u][5] + k1.y);
        Xs[row * FP_XPITCH + col + 6] = tanhf(acc[u][6] + k1.z);
        Xs[row * FP_XPITCH + col + 7] = tanhf(acc[u][7] + k1.w);
    }
    __syncthreads();

    int wid = tid >> 5, lane = tid & 31;
    for (int rr = wid * 8; rr < wid * 8 + 8; rr++) {
        int ns = s_nx[rr];
        int idx = (ns < NUM_C) ? ns : (NUM_C - 1);
        const float* pw = p_W + idx * DIM;
        float a = 0.f;
        #pragma unroll
        for (int q = 0; q < 4; q++)
            a = fmaf(Xs[rr * FP_XPITCH + lane + 32 * q], pw[lane + 32 * q], a);
        #pragma unroll
        for (int off = 16; off; off >>= 1) a += __shfl_xor_sync(~0u, a, off);
        if (lane == 0) {
            float pr = sigmoidf_(a + p_b[idx]);
            out[row0 + rr] = (ns < NUM_C) ? pr : 0.f;
        }
    }
}

// ---------------- launch: forked-capture stream graph ----------------------
extern "C" void kernel_launch(void* const* d_in, const int* in_sizes, int n_in,
                              void* d_out, int out_size) {
    const int*   skill  = (const int*)d_in[0];
    const int*   answer = (const int*)d_in[1];
    const float* k_emb  = (const float*)d_in[2];
    const float* v_emb  = (const float*)d_in[3];
    const float* Mk     = (const float*)d_in[4];
    const float* Mv0    = (const float*)d_in[5];
    const float* f_W    = (const float*)d_in[6];
    const float* f_b    = (const float*)d_in[7];
    const float* p_W    = (const float*)d_in[8];
    const float* p_b    = (const float*)d_in[9];
    const float* e_W    = (const float*)d_in[10];
    const float* e_b    = (const float*)d_in[11];
    const float* a_W    = (const float*)d_in[12];
    const float* a_b    = (const float*)d_in[13];
    float* out = (float*)d_out;

    static cudaStream_t sA = nullptr, sB = nullptr, sC = nullptr;
    static cudaEvent_t evR = nullptr, evA = nullptr, evB = nullptr, evC = nullptr;
    if (!sA) {   // first call = correctness run (not captured): safe to create
        cudaStreamCreateWithFlags(&sA, cudaStreamNonBlocking);
        cudaStreamCreateWithFlags(&sB, cudaStreamNonBlocking);
        cudaStreamCreateWithFlags(&sC, cudaStreamNonBlocking);
        cudaEventCreateWithFlags(&evR, cudaEventDisableTiming);
        cudaEventCreateWithFlags(&evA, cudaEventDisableTiming);
        cudaEventCreateWithFlags(&evB, cudaEventDisableTiming);
        cudaEventCreateWithFlags(&evC, cudaEventDisableTiming);
        cudaFuncSetAttribute(k_fpred, cudaFuncAttributeMaxDynamicSharedMemorySize, FP_SMEM);
    }

    cudaEventRecord(evR, 0);
    cudaStreamWaitEvent(sA, evR, 0);
    cudaStreamWaitEvent(sB, evR, 0);
    cudaStreamWaitEvent(sC, evR, 0);

    k_wtable<<<125, 256, 0, sA>>>(k_emb, Mk);
    k_ea    <<<125, 256, 0, sB>>>(v_emb, e_b, a_b, e_W, a_W);
    k_kfT   <<<71, 256, 0, sC>>>(k_emb, f_b, f_W);      // overlaps scan phases

    cudaEventRecord(evA, sA);
    cudaEventRecord(evB, sB);
    cudaEventRecord(evC, sC);

    cudaStreamWaitEvent(0, evA, 0);
    cudaStreamWaitEvent(0, evB, 0);
    k_scanA<<<dim3(NCH - 1, 512), 128>>>(skill, answer);
    k_scanB<<<SLICE / 256, 256>>>(Mv0);
    k_scanC<<<dim3(NCH, 512), 128>>>(skill, answer);

    cudaStreamWaitEvent(0, evC, 0);
    k_fpred<<<199, 256, FP_SMEM>>>(skill, p_W, p_b, out);
}

// round 16
// speedup vs baseline: 1.1762x; 1.1762x over previous
#include <cuda_runtime.h>

#define BATCH 64
#define TT    200
#define NUM_C 2000
#define DIM   128
#define MM    50
#define MP    56          // M padded; rows 50..55 have w=0 (inert)
#define NX    4000        // distinct x = skill + 2000*answer

// ---------------- scratch (device globals; no allocation allowed) ----------
__device__ __align__(16) float g_w[NUM_C * MP];       // softmax(k·Mk^T) per skill id
__device__ __align__(16) float g_ea[NX * 256];        // [x][0:128]=e, [128:256]=a
__device__ __align__(16) float g_kf[NUM_C * DIM];     // k-part of f GEMM + f_b folded
__device__ __align__(16) float g_reads[BATCH * TT * DIM];
__device__ __align__(16) float g_fWat[DIM * DIM];     // [k][i] = f_W[i*256 + k]

__device__ __forceinline__ float sigmoidf_(float x) { return 1.f / (1.f + __expf(-x)); }

// =====================================================================
// w table: softmax(k_emb[c] · Mk^T) over 50 slots; 125 CTAs
// =====================================================================
__global__ void k_wtable(const float* __restrict__ k_emb, const float* __restrict__ Mk) {
    __shared__ float mksh[DIM * 65];   // padded transpose, conflict-free
    __shared__ float ksh[4 * DIM];
    __shared__ float gmax[8], gsum[8];
    int tid = threadIdx.x;
    int c0 = blockIdx.x * 16;
    int m = tid & 63, cg = tid >> 6, wh = (tid >> 5) & 1;
    for (int i = tid; i < MM * DIM; i += 256) {
        int mm = i >> 7, j = i & 127;
        mksh[j * 65 + mm] = Mk[i];
    }
    for (int cl = 0; cl < 16; cl += 4) {
        int c = c0 + cl + cg;
        __syncthreads();
        for (int j = tid; j < 4 * DIM; j += 256)
            ksh[j] = k_emb[(c0 + cl + (j >> 7)) * DIM + (j & 127)];
        __syncthreads();
        float acc = 0.f;
        if (m < MM) {
            #pragma unroll 8
            for (int j = 0; j < DIM; j++) acc = fmaf(ksh[cg * DIM + j], mksh[j * 65 + m], acc);
        }
        float lg = (m < MM) ? acc : -1e30f;
        float mx = lg;
        #pragma unroll
        for (int off = 16; off; off >>= 1) mx = fmaxf(mx, __shfl_xor_sync(~0u, mx, off));
        if ((tid & 31) == 0) gmax[cg * 2 + wh] = mx;
        __syncthreads();
        mx = fmaxf(gmax[cg * 2], gmax[cg * 2 + 1]);
        float ex = (m < MM) ? __expf(lg - mx) : 0.f;
        float sv = ex;
        #pragma unroll
        for (int off = 16; off; off >>= 1) sv += __shfl_xor_sync(~0u, sv, off);
        if ((tid & 31) == 0) gsum[cg * 2 + wh] = sv;
        __syncthreads();
        float s = gsum[cg * 2] + gsum[cg * 2 + 1];
        if (m < MP) g_w[c * MP + m] = ex / s;
    }
}

// =====================================================================
// e/a table: 4000 x 256 GEMM (K=128) + activations; 125 CTAs
// =====================================================================
__global__ void k_ea(const float* __restrict__ v_emb, const float* __restrict__ e_b,
                     const float* __restrict__ a_b,
                     const float* __restrict__ e_W, const float* __restrict__ a_W) {
    __shared__ float Xs[32 * DIM];
    __shared__ __align__(16) float Ws[16 * 260];
    int row0 = blockIdx.x * 32;
    int tid = threadIdx.x;
    int tx = tid & 31, ty = tid >> 5;
    for (int i = tid; i < 32 * DIM; i += 256) Xs[i] = v_emb[row0 * DIM + i];
    float acc[4][8];
    #pragma unroll
    for (int u = 0; u < 4; u++)
        #pragma unroll
        for (int v = 0; v < 8; v++) acc[u][v] = 0.f;
    for (int kc = 0; kc < DIM; kc += 16) {
        __syncthreads();
        for (int i = tid; i < 16 * 256; i += 256) {
            int kk = i & 15, c = i >> 4;
            float v = (c < DIM) ? e_W[c * DIM + kc + kk] : a_W[(c - DIM) * DIM + kc + kk];
            Ws[kk * 260 + c] = v;
        }
        __syncthreads();
        #pragma unroll
        for (int kk = 0; kk < 16; kk++) {
            float xv[4];
            #pragma unroll
            for (int u = 0; u < 4; u++) xv[u] = Xs[(ty * 4 + u) * DIM + kc + kk];
            float4 w0 = *(const float4*)&Ws[kk * 260 + tx * 8];
            float4 w1 = *(const float4*)&Ws[kk * 260 + tx * 8 + 4];
            #pragma unroll
            for (int u = 0; u < 4; u++) {
                acc[u][0] = fmaf(xv[u], w0.x, acc[u][0]);
                acc[u][1] = fmaf(xv[u], w0.y, acc[u][1]);
                acc[u][2] = fmaf(xv[u], w0.z, acc[u][2]);
                acc[u][3] = fmaf(xv[u], w0.w, acc[u][3]);
                acc[u][4] = fmaf(xv[u], w1.x, acc[u][4]);
                acc[u][5] = fmaf(xv[u], w1.y, acc[u][5]);
                acc[u][6] = fmaf(xv[u], w1.z, acc[u][6]);
                acc[u][7] = fmaf(xv[u], w1.w, acc[u][7]);
            }
        }
    }
    int col = tx * 8;
    float barr[8];
    #pragma unroll
    for (int v = 0; v < 8; v++) {
        int cc = col + v;
        barr[v] = (cc < DIM) ? e_b[cc] : a_b[cc - DIM];
    }
    #pragma unroll
    for (int u = 0; u < 4; u++) {
        float o[8];
        #pragma unroll
        for (int v = 0; v < 8; v++) {
            float z = acc[u][v] + barr[v];
            o[v] = (col + v < DIM) ? sigmoidf_(z) : tanhf(z);
        }
        int r = row0 + ty * 4 + u;
        *(float4*)&g_ea[r * 256 + col]     = make_float4(o[0], o[1], o[2], o[3]);
        *(float4*)&g_ea[r * 256 + col + 4] = make_float4(o[4], o[5], o[6], o[7]);
    }
}

// =====================================================================
// kf table (63 CTAs) + f_W(reads-half) transpose (8 CTAs)
// =====================================================================
__global__ void k_kfT(const float* __restrict__ k_emb, const float* __restrict__ f_b,
                      const float* __restrict__ f_W) {
    __shared__ float Xs[32 * DIM];
    __shared__ __align__(16) float Ws[16 * 132];
    int bid = blockIdx.x;
    int tid = threadIdx.x;
    if (bid >= 63) {
        int base = (bid - 63) * 2048;
        #pragma unroll
        for (int j = 0; j < 8; j++) {
            int idx = base + j * 256 + tid;
            int k = idx >> 7, ii = idx & 127;
            g_fWat[idx] = f_W[ii * 256 + k];
        }
        return;
    }
    int row0 = bid * 32;
    for (int i = tid; i < 32 * DIM; i += 256) {
        int rr = i >> 7;
        Xs[i] = (row0 + rr < NUM_C) ? k_emb[row0 * DIM + i] : 0.f;
    }
    int tx = tid & 31, ty = tid >> 5;
    float acc[4][4];
    #pragma unroll
    for (int u = 0; u < 4; u++)
        #pragma unroll
        for (int v = 0; v < 4; v++) acc[u][v] = 0.f;
    for (int kc = 0; kc < DIM; kc += 16) {
        __syncthreads();
        for (int i = tid; i < 16 * DIM; i += 256) {
            int kk = i & 15, col = i >> 4;
            Ws[kk * 132 + col] = f_W[col * 256 + 128 + kc + kk];
        }
        __syncthreads();
        #pragma unroll
        for (int kk = 0; kk < 16; kk++) {
            float4 w0 = *(const float4*)&Ws[kk * 132 + tx * 4];
            #pragma unroll
            for (int u = 0; u < 4; u++) {
                float x = Xs[(ty * 4 + u) * DIM + kc + kk];
                acc[u][0] = fmaf(x, w0.x, acc[u][0]);
                acc[u][1] = fmaf(x, w0.y, acc[u][1]);
                acc[u][2] = fmaf(x, w0.z, acc[u][2]);
                acc[u][3] = fmaf(x, w0.w, acc[u][3]);
            }
        }
    }
    int col = tx * 4;
    float b0 = f_b[col], b1 = f_b[col + 1], b2 = f_b[col + 2], b3 = f_b[col + 3];
    #pragma unroll
    for (int u = 0; u < 4; u++) {
        int r = row0 + ty * 4 + u;
        if (r < NUM_C)
            *(float4*)&g_kf[r * DIM + col] =
                make_float4(acc[u][0] + b0, acc[u][1] + b1, acc[u][2] + b2, acc[u][3] + b3);
    }
}

// =====================================================================
// Scan: 512 CTAs = 64 b x 8 d-slices of 16, **160 threads**:
// 4 compute warps (R9 step math, depth-4 rotation, 1 sync/step) +
// 1 reducer warp. Compute warps STS partial acc into ping-pong red[2][128]
// (no shfl, no STG on their path); reducer warp sums step t-1's buffer
// (disjoint parity -> race-free across the single per-step barrier)
// and writes g_reads.
// =====================================================================
__global__ __launch_bounds__(160) void k_scan(const int* __restrict__ skill,
                                              const int* __restrict__ answer,
                                              const float* __restrict__ Mv0) {
    __shared__ int s_sk[TT], s_x[TT];
    __shared__ __align__(16) float w_sh[4][MP];
    __shared__ __align__(16) float e_sh[4][16];
    __shared__ __align__(16) float a_sh[4][16];
    __shared__ __align__(16) float red[2][128];   // [parity][mg*16 + ddl]
    int b = blockIdx.x >> 3;
    int dbase = (blockIdx.x & 7) * 16;
    int tid = threadIdx.x;
    int wid = tid >> 5, lane = tid & 31;
    int mg = lane >> 2, dq = lane & 3;
    int ddl = wid * 4 + dq;                // 0..15 within slice (compute warps)
    bool comp = tid < 128;

    for (int t = tid; t < TT; t += 160) {
        int s = skill[b * TT + t];
        int aa = answer[b * TT + t];
        if (aa > 1) aa = 1;
        s_sk[t] = s;
        s_x[t] = s + NUM_C * aa;
    }

    float mv[7];
    if (comp) {
        #pragma unroll
        for (int i = 0; i < 7; i++) {
            int m = mg * 7 + i;
            mv[i] = (m < MM) ? Mv0[m * DIM + dbase + ddl] : 0.f;
        }
    }
    __syncthreads();   // s_sk/s_x visible

    // gather roles (all within compute warps): tid<56 w, [64,80) e, [80,96) a
    bool isW = tid < MP;
    bool isE = (tid >= 64) && (tid < 80);
    bool isA = (tid >= 80) && (tid < 96);
    bool lp = isW || isE || isA;
    int eoff = isE ? (dbase + (tid - 64)) : (128 + dbase + (tid - 80));

    float pfR[4];
    pfR[0] = 0.f; pfR[1] = 0.f; pfR[2] = 0.f; pfR[3] = 0.f;
    if (lp) {
        float v0;
        if (isW) {
            v0     = g_w[s_sk[0] * MP + tid];
            pfR[1] = g_w[s_sk[1] * MP + tid];
            pfR[2] = g_w[s_sk[2] * MP + tid];
            pfR[3] = g_w[s_sk[3] * MP + tid];
            w_sh[0][tid] = v0;
        } else {
            v0     = g_ea[s_x[0] * 256 + eoff];
            pfR[1] = g_ea[s_x[1] * 256 + eoff];
            pfR[2] = g_ea[s_x[2] * 256 + eoff];
            pfR[3] = g_ea[s_x[3] * 256 + eoff];
            if (isE) e_sh[0][tid - 64] = v0;
            else     a_sh[0][tid - 80] = v0;
        }
    }
    __syncthreads();

    int outbase = (b * TT) * DIM + dbase;      // reducer adds + lane
    int redidx = mg * 16 + ddl;

    for (int t0 = 0; t0 < TT; t0 += 4) {
        #pragma unroll
        for (int q = 0; q < 4; q++) {
            int t = t0 + q;
            if (comp) {
                // ---- compute step t from buffers[q] ----
                float e = e_sh[q][ddl];
                float a = a_sh[q][ddl];
                float acc = 0.f;
                #pragma unroll
                for (int i = 0; i < 7; i++) {
                    float wm = w_sh[q][mg * 7 + i];
                    acc = fmaf(wm, mv[i], acc);                  // PRE-update read
                    mv[i] = fmaf(wm, fmaf(-e, mv[i], a), mv[i]);
                }
                red[t & 1][redidx] = acc;
                // ---- STS buffers for step t+1 (value loaded at t-3) ----
                if (lp && t + 1 < TT) {
                    float pv = pfR[(q + 1) & 3];
                    int nb = (q + 1) & 3;
                    if (isW)      w_sh[nb][tid] = pv;
                    else if (isE) e_sh[nb][tid - 64] = pv;
                    else          a_sh[nb][tid - 80] = pv;
                }
                // ---- LDG gather for step t+4 into just-freed slot q ----
                if (lp && t + 4 < TT) {
                    float nv;
                    if (isW) nv = g_w[s_sk[t + 4] * MP + tid];
                    else     nv = g_ea[s_x[t + 4] * 256 + eoff];
                    pfR[q] = nv;
                }
            } else if (t > 0 && lane < 16) {
                // ---- reducer: sum step t-1's partials, write g_reads ----
                int p = (t - 1) & 1;
                float s = red[p][lane] + red[p][16 + lane];
                s += red[p][32 + lane] + red[p][48 + lane];
                s += red[p][64 + lane] + red[p][80 + lane];
                s += red[p][96 + lane] + red[p][112 + lane];
                g_reads[outbase + (t - 1) * DIM + lane] = s;
            }
            __syncthreads();
        }
    }
    // final step's reduction (t = TT-1, parity 1)
    if (!comp && lane < 16) {
        float s = red[1][lane] + red[1][16 + lane];
        s += red[1][32 + lane] + red[1][48 + lane];
        s += red[1][64 + lane] + red[1][80 + lane];
        s += red[1][96 + lane] + red[1][112 + lane];
        g_reads[outbase + (TT - 1) * DIM + lane] = s;
    }
}

// =====================================================================
// fpred v2 (R14-proven): full fWat in 64KB dynamic smem, zero mainloop
// barriers. 199 CTAs x 64 rows, 256 threads.
// =====================================================================
#define FP_XPITCH 132
#define FP_SMEM ((64 * FP_XPITCH + DIM * DIM) * 4)
__global__ __launch_bounds__(256) void k_fpred(const int* __restrict__ skill,
                                               const float* __restrict__ p_W,
                                               const float* __restrict__ p_b,
                                               float* __restrict__ out) {
    extern __shared__ __align__(16) float dsm[];
    float* Xs = dsm;
    float* Ws = dsm + 64 * FP_XPITCH;
    __shared__ int s_kf[64], s_nx[64];
    int row0 = blockIdx.x * 64;
    int tid = threadIdx.x;

    if (tid < 64) {
        int r = row0 + tid;
        int bb = r / 199;
        int t = r - bb * 199;
        s_kf[tid] = skill[bb * TT + t];
        s_nx[tid] = skill[bb * TT + t + 1];
    }
    for (int i = tid * 4; i < DIM * DIM; i += 1024)
        *(float4*)&Ws[i] = *(const float4*)&g_fWat[i];
    {
        int row = tid >> 2, qr = tid & 3;
        int r = row0 + row;
        int bb = r / 199;
        int t = r - bb * 199;
        const float* src = &g_reads[(bb * TT + t) * DIM];
        #pragma unroll
        for (int j = 0; j < 8; j++) {
            int c4 = (qr + j * 4) * 4;
            *(float4*)&Xs[row * FP_XPITCH + c4] = *(const float4*)&src[c4];
        }
    }
    __syncthreads();

    int tx = tid & 15, ty = tid >> 4;
    float acc[4][8];
    #pragma unroll
    for (int u = 0; u < 4; u++)
        #pragma unroll
        for (int v = 0; v < 8; v++) acc[u][v] = 0.f;

    #pragma unroll 4
    for (int k = 0; k < DIM; k += 4) {
        float4 x0 = *(const float4*)&Xs[(ty * 4 + 0) * FP_XPITCH + k];
        float4 x1 = *(const float4*)&Xs[(ty * 4 + 1) * FP_XPITCH + k];
        float4 x2 = *(const float4*)&Xs[(ty * 4 + 2) * FP_XPITCH + k];
        float4 x3 = *(const float4*)&Xs[(ty * 4 + 3) * FP_XPITCH + k];
        #pragma unroll
        for (int kk = 0; kk < 4; kk++) {
            float4 w0 = *(const float4*)&Ws[(k + kk) * DIM + tx * 8];
            float4 w1 = *(const float4*)&Ws[(k + kk) * DIM + tx * 8 + 4];
            float xv[4];
            xv[0] = (kk == 0) ? x0.x : (kk == 1) ? x0.y : (kk == 2) ? x0.z : x0.w;
            xv[1] = (kk == 0) ? x1.x : (kk == 1) ? x1.y : (kk == 2) ? x1.z : x1.w;
            xv[2] = (kk == 0) ? x2.x : (kk == 1) ? x2.y : (kk == 2) ? x2.z : x2.w;
            xv[3] = (kk == 0) ? x3.x : (kk == 1) ? x3.y : (kk == 2) ? x3.z : x3.w;
            #pragma unroll
            for (int u = 0; u < 4; u++) {
                acc[u][0] = fmaf(xv[u], w0.x, acc[u][0]);
                acc[u][1] = fmaf(xv[u], w0.y, acc[u][1]);
                acc[u][2] = fmaf(xv[u], w0.z, acc[u][2]);
                acc[u][3] = fmaf(xv[u], w0.w, acc[u][3]);
                acc[u][4] = fmaf(xv[u], w1.x, acc[u][4]);
                acc[u][5] = fmaf(xv[u], w1.y, acc[u][5]);
                acc[u][6] = fmaf(xv[u], w1.z, acc[u][6]);
                acc[u][7] = fmaf(xv[u], w1.w, acc[u][7]);
            }
        }
    }
    __syncthreads();

    int col = tx * 8;
    #pragma unroll
    for (int u = 0; u < 4; u++) {
        int row = ty * 4 + u;
        int sc = s_kf[row];
        float4 k0 = *(const float4*)&g_kf[sc * DIM + col];
        float4 k1 = *(const float4*)&g_kf[sc * DIM + col + 4];
        Xs[row * FP_XPITCH + col + 0] = tanhf(acc[u][0] + k0.x);
        Xs[row * FP_XPITCH + col + 1] = tanhf(acc[u][1] + k0.y);
        Xs[row * FP_XPITCH + col + 2] = tanhf(acc[u][2] + k0.z);
        Xs[row * FP_XPITCH + col + 3] = tanhf(acc[u][3] + k0.w);
        Xs[row * FP_XPITCH + col + 4] = tanhf(acc[u][4] + k1.x);
        Xs[row * FP_XPITCH + col + 5] = tanhf(acc[u][5] + k1.y);
        Xs[row * FP_XPITCH + col + 6] = tanhf(acc[u][6] + k1.z);
        Xs[row * FP_XPITCH + col + 7] = tanhf(acc[u][7] + k1.w);
    }
    __syncthreads();

    int wid = tid >> 5, lane = tid & 31;
    for (int rr = wid * 8; rr < wid * 8 + 8; rr++) {
        int ns = s_nx[rr];
        int idx = (ns < NUM_C) ? ns : (NUM_C - 1);
        const float* pw = p_W + idx * DIM;
        float a = 0.f;
        #pragma unroll
        for (int q = 0; q < 4; q++)
            a = fmaf(Xs[rr * FP_XPITCH + lane + 32 * q], pw[lane + 32 * q], a);
        #pragma unroll
        for (int off = 16; off; off >>= 1) a += __shfl_xor_sync(~0u, a, off);
        if (lane == 0) {
            float pr = sigmoidf_(a + p_b[idx]);
            out[row0 + rr] = (ns < NUM_C) ? pr : 0.f;
        }
    }
}

// ---------------- launch: forked-capture stream graph ----------------------
extern "C" void kernel_launch(void* const* d_in, const int* in_sizes, int n_in,
                              void* d_out, int out_size) {
    const int*   skill  = (const int*)d_in[0];
    const int*   answer = (const int*)d_in[1];
    const float* k_emb  = (const float*)d_in[2];
    const float* v_emb  = (const float*)d_in[3];
    const float* Mk     = (const float*)d_in[4];
    const float* Mv0    = (const float*)d_in[5];
    const float* f_W    = (const float*)d_in[6];
    const float* f_b    = (const float*)d_in[7];
    const float* p_W    = (const float*)d_in[8];
    const float* p_b    = (const float*)d_in[9];
    const float* e_W    = (const float*)d_in[10];
    const float* e_b    = (const float*)d_in[11];
    const float* a_W    = (const float*)d_in[12];
    const float* a_b    = (const float*)d_in[13];
    float* out = (float*)d_out;

    static cudaStream_t sA = nullptr, sB = nullptr, sC = nullptr;
    static cudaEvent_t evR = nullptr, evA = nullptr, evB = nullptr, evC = nullptr;
    if (!sA) {   // first call = correctness run (not captured): safe to create
        cudaStreamCreateWithFlags(&sA, cudaStreamNonBlocking);
        cudaStreamCreateWithFlags(&sB, cudaStreamNonBlocking);
        cudaStreamCreateWithFlags(&sC, cudaStreamNonBlocking);
        cudaEventCreateWithFlags(&evR, cudaEventDisableTiming);
        cudaEventCreateWithFlags(&evA, cudaEventDisableTiming);
        cudaEventCreateWithFlags(&evB, cudaEventDisableTiming);
        cudaEventCreateWithFlags(&evC, cudaEventDisableTiming);
        cudaFuncSetAttribute(k_fpred, cudaFuncAttributeMaxDynamicSharedMemorySize, FP_SMEM);
    }

    cudaEventRecord(evR, 0);
    cudaStreamWaitEvent(sA, evR, 0);
    cudaStreamWaitEvent(sB, evR, 0);
    cudaStreamWaitEvent(sC, evR, 0);

    k_wtable<<<125, 256, 0, sA>>>(k_emb, Mk);
    k_ea    <<<125, 256, 0, sB>>>(v_emb, e_b, a_b, e_W, a_W);
    k_kfT   <<<71, 256, 0, sC>>>(k_emb, f_b, f_W);      // overlaps scan

    cudaEventRecord(evA, sA);
    cudaEventRecord(evB, sB);
    cudaEventRecord(evC, sC);

    cudaStreamWaitEvent(0, evA, 0);
    cudaStreamWaitEvent(0, evB, 0);
    k_scan<<<512, 160>>>(skill, answer, Mv0);

    cudaStreamWaitEvent(0, evC, 0);
    k_fpred<<<199, 256, FP_SMEM>>>(skill, p_W, p_b, out);
}